// round 1
// baseline (speedup 1.0000x reference)
#include <cuda_runtime.h>
#include <math.h>

// Problem constants
#define B_   2
#define H_   1080
#define W_   1920
#define SH_  540
#define SW_  960
#define HW_  (H_*W_)
#define SHW_ (SH_*SW_)

// Scratch (device globals — no allocations allowed)
__device__ float  g_luma[B_*SHW_];
__device__ float  g_edge[B_*SHW_];
__device__ float  g_tmp [B_*SHW_];
__device__ float2 g_grad_half[B_*SHW_];
__device__ float2 g_grad_full[B_*HW_];   // ~33 MB

// ---------------------------------------------------------------------------
// helpers
// ---------------------------------------------------------------------------
__device__ __forceinline__ float sampX(const float* __restrict__ p, int W, int r, float x) {
    // 1-D bilinear along x at integer row r, border clamp (align_corners convention)
    x = fminf(fmaxf(x, 0.f), (float)(W - 1));
    int x0 = (int)x;
    int x1 = min(x0 + 1, W - 1);
    float w = x - (float)x0;
    const float* row = p + (size_t)r * W;
    float a = __ldg(row + x0);
    float b = __ldg(row + x1);
    return a + (b - a) * w;
}

// sobel_x pair at integer row r, column j:  (right-left, left+2c+right)
__device__ __forceinline__ float2 sxyRow(const float* __restrict__ p, int W, int r, int j, float sx) {
    float left  = sampX(p, W, r, (float)j - sx);
    float right = sampX(p, W, r, (float)j + sx);
    float c     = __ldg(p + (size_t)r * W + j);
    return make_float2(right - left, left + 2.f * c + right);
}

// sxy pair sampled at fractional row y (border clamp, linear in y)
__device__ __forceinline__ float2 sxyAt(const float* __restrict__ p, int H, int W, float y, int j, float sx) {
    y = fminf(fmaxf(y, 0.f), (float)(H - 1));
    int r0 = (int)y;
    int r1 = min(r0 + 1, H - 1);
    float w = y - (float)r0;
    float2 a = sxyRow(p, W, r0, j, sx);
    float2 b = sxyRow(p, W, r1, j, sx);
    return make_float2(a.x + (b.x - a.x) * w, a.y + (b.y - a.y) * w);
}

// ---------------------------------------------------------------------------
// k1: luma + downsample 1080x1920 -> 540x960 (align_corners)
// ---------------------------------------------------------------------------
__global__ void __launch_bounds__(256) k_luma_half(const float* __restrict__ img) {
    int j = blockIdx.x * 32 + threadIdx.x;
    int i = blockIdx.y * 8  + threadIdx.y;
    int b = blockIdx.z;
    if (j >= SW_ || i >= SH_) return;

    float ys = fminf((float)i * (1079.0f / 539.0f), 1079.0f);
    float xs = fminf((float)j * (1919.0f / 959.0f), 1919.0f);
    int y0 = (int)ys, x0 = (int)xs;
    int y1 = min(y0 + 1, H_ - 1), x1 = min(x0 + 1, W_ - 1);
    float wy = ys - (float)y0, wx = xs - (float)x0;

    const float* r0c = img + (size_t)b * 3 * HW_;
    const float* g0c = r0c + HW_;
    const float* b0c = r0c + 2 * HW_;

    int i00 = y0 * W_ + x0, i01 = y0 * W_ + x1, i10 = y1 * W_ + x0, i11 = y1 * W_ + x1;
    float v00 = 0.299f*__ldg(r0c+i00) + 0.587f*__ldg(g0c+i00) + 0.114f*__ldg(b0c+i00);
    float v01 = 0.299f*__ldg(r0c+i01) + 0.587f*__ldg(g0c+i01) + 0.114f*__ldg(b0c+i01);
    float v10 = 0.299f*__ldg(r0c+i10) + 0.587f*__ldg(g0c+i10) + 0.114f*__ldg(b0c+i10);
    float v11 = 0.299f*__ldg(r0c+i11) + 0.587f*__ldg(g0c+i11) + 0.114f*__ldg(b0c+i11);

    float v = (v00 * (1.f - wx) + v01 * wx) * (1.f - wy)
            + (v10 * (1.f - wx) + v11 * wx) * wy;
    g_luma[(size_t)b * SHW_ + i * SW_ + j] = v;
}

// ---------------------------------------------------------------------------
// k2: fused sobel_x + sobel_y (offset 1.0) -> edge magnitude
// ---------------------------------------------------------------------------
__global__ void __launch_bounds__(256) k_sobel_edge() {
    int j = blockIdx.x * 32 + threadIdx.x;
    int i = blockIdx.y * 8  + threadIdx.y;
    int b = blockIdx.z;
    if (j >= SW_ || i >= SH_) return;

    const float sx = 1.0f * (float)(SW_ - 1) / (float)SW_;
    const float sy = 1.0f * (float)(SH_ - 1) / (float)SH_;
    const float* p = g_luma + (size_t)b * SHW_;

    float2 top = sxyAt (p, SH_, SW_, (float)i - sy, j, sx);
    float2 mid = sxyRow(p, SW_, i, j, sx);
    float2 bot = sxyAt (p, SH_, SW_, (float)i + sy, j, sx);

    float xg = (top.x + 2.f * mid.x + bot.x) * 0.125f;
    float yg = (bot.y - top.y) * 0.125f;
    float mag = sqrtf(xg * xg + yg * yg);
    g_edge[(size_t)b * SHW_ + i * SW_ + j] = powf(mag, 0.7f);
}

// ---------------------------------------------------------------------------
// k3: separable 5-tap gaussian (sigma=1, replicate padding)
// ---------------------------------------------------------------------------
#define GW0 0.4026199469f
#define GW1 0.2442013420f
#define GW2 0.0544886845f

__global__ void __launch_bounds__(256) k_blur_h() {
    int j = blockIdx.x * 32 + threadIdx.x;
    int i = blockIdx.y * 8  + threadIdx.y;
    int b = blockIdx.z;
    if (j >= SW_ || i >= SH_) return;
    const float* row = g_edge + (size_t)b * SHW_ + (size_t)i * SW_;
    int jm2 = max(j - 2, 0), jm1 = max(j - 1, 0);
    int jp1 = min(j + 1, SW_ - 1), jp2 = min(j + 2, SW_ - 1);
    float v = GW2 * (__ldg(row + jm2) + __ldg(row + jp2))
            + GW1 * (__ldg(row + jm1) + __ldg(row + jp1))
            + GW0 * __ldg(row + j);
    g_tmp[(size_t)b * SHW_ + i * SW_ + j] = v;
}

__global__ void __launch_bounds__(256) k_blur_v() {
    int j = blockIdx.x * 32 + threadIdx.x;
    int i = blockIdx.y * 8  + threadIdx.y;
    int b = blockIdx.z;
    if (j >= SW_ || i >= SH_) return;
    const float* p = g_tmp + (size_t)b * SHW_;
    int im2 = max(i - 2, 0), im1 = max(i - 1, 0);
    int ip1 = min(i + 1, SH_ - 1), ip2 = min(i + 2, SH_ - 1);
    float v = GW2 * (__ldg(p + (size_t)im2 * SW_ + j) + __ldg(p + (size_t)ip2 * SW_ + j))
            + GW1 * (__ldg(p + (size_t)im1 * SW_ + j) + __ldg(p + (size_t)ip1 * SW_ + j))
            + GW0 * __ldg(p + (size_t)i * SW_ + j);
    g_edge[(size_t)b * SHW_ + i * SW_ + j] = v;
}

// ---------------------------------------------------------------------------
// k4: fused sobel pair (offset 0.5) on blurred edge -> grad_field half (float2)
// ---------------------------------------------------------------------------
__global__ void __launch_bounds__(256) k_sobel_grad() {
    int j = blockIdx.x * 32 + threadIdx.x;
    int i = blockIdx.y * 8  + threadIdx.y;
    int b = blockIdx.z;
    if (j >= SW_ || i >= SH_) return;

    const float sx = 0.5f * (float)(SW_ - 1) / (float)SW_;
    const float sy = 0.5f * (float)(SH_ - 1) / (float)SH_;
    const float* p = g_edge + (size_t)b * SHW_;

    float2 top = sxyAt (p, SH_, SW_, (float)i - sy, j, sx);
    float2 mid = sxyRow(p, SW_, i, j, sx);
    float2 bot = sxyAt (p, SH_, SW_, (float)i + sy, j, sx);

    float xg = (top.x + 2.f * mid.x + bot.x) * 0.125f;
    float yg = (bot.y - top.y) * 0.125f;
    g_grad_half[(size_t)b * SHW_ + i * SW_ + j] = make_float2(xg, yg);
}

// ---------------------------------------------------------------------------
// k5: resize grad_field 540x960 -> 1080x1920 (align_corners bilinear)
// ---------------------------------------------------------------------------
__global__ void __launch_bounds__(256) k_resize_grad() {
    int j = blockIdx.x * 32 + threadIdx.x;
    int i = blockIdx.y * 8  + threadIdx.y;
    int b = blockIdx.z;
    if (j >= W_ || i >= H_) return;

    float ys = fminf((float)i * (539.0f / 1079.0f), (float)(SH_ - 1));
    float xs = fminf((float)j * (959.0f / 1919.0f), (float)(SW_ - 1));
    int y0 = (int)ys, x0 = (int)xs;
    int y1 = min(y0 + 1, SH_ - 1), x1 = min(x0 + 1, SW_ - 1);
    float wy = ys - (float)y0, wx = xs - (float)x0;

    const float2* p = g_grad_half + (size_t)b * SHW_;
    float2 v00 = p[(size_t)y0 * SW_ + x0], v01 = p[(size_t)y0 * SW_ + x1];
    float2 v10 = p[(size_t)y1 * SW_ + x0], v11 = p[(size_t)y1 * SW_ + x1];
    float2 r;
    r.x = (v00.x * (1.f - wx) + v01.x * wx) * (1.f - wy) + (v10.x * (1.f - wx) + v11.x * wx) * wy;
    r.y = (v00.y * (1.f - wx) + v01.y * wx) * (1.f - wy) + (v10.y * (1.f - wx) + v11.y * wx) * wy;
    g_grad_full[(size_t)b * HW_ + i * W_ + j] = r;
}

// ---------------------------------------------------------------------------
// k6: iterative warp + final image sample + clip
// ---------------------------------------------------------------------------
__global__ void __launch_bounds__(256) k_warp(const float* __restrict__ img, float* __restrict__ out) {
    int j = blockIdx.x * 32 + threadIdx.x;
    int i = blockIdx.y * 8  + threadIdx.y;
    int b = blockIdx.z;
    if (j >= W_ || i >= H_) return;

    const float2* g = g_grad_full + (size_t)b * HW_;
    // step in pixel units: relstr * (W-1)/W   (relstr = H/1080*0.1 = 0.1)
    const float stx = 0.1f * (float)(W_ - 1) / (float)W_;
    const float sty = 0.1f * (float)(H_ - 1) / (float)H_;

    float px = (float)j, py = (float)i;
#pragma unroll
    for (int it = 0; it < 6; it++) {
        float xc = fminf(fmaxf(px, 0.f), (float)(W_ - 1));
        float yc = fminf(fmaxf(py, 0.f), (float)(H_ - 1));
        int x0 = (int)xc, y0 = (int)yc;
        int x1 = min(x0 + 1, W_ - 1), y1 = min(y0 + 1, H_ - 1);
        float wx = xc - (float)x0, wy = yc - (float)y0;
        float2 v00 = __ldg(&g[(size_t)y0 * W_ + x0]);
        float2 v01 = __ldg(&g[(size_t)y0 * W_ + x1]);
        float2 v10 = __ldg(&g[(size_t)y1 * W_ + x0]);
        float2 v11 = __ldg(&g[(size_t)y1 * W_ + x1]);
        float dx = (v00.x * (1.f - wx) + v01.x * wx) * (1.f - wy)
                 + (v10.x * (1.f - wx) + v11.x * wx) * wy;
        float dy = (v00.y * (1.f - wx) + v01.y * wx) * (1.f - wy)
                 + (v10.y * (1.f - wx) + v11.y * wx) * wy;
        float inv = 1.f / (sqrtf(dx * dx + dy * dy) + 0.01f);
        px -= dx * inv * stx;
        py -= dy * inv * sty;
    }

    // final image sample (3 channels) + clip
    float xc = fminf(fmaxf(px, 0.f), (float)(W_ - 1));
    float yc = fminf(fmaxf(py, 0.f), (float)(H_ - 1));
    int x0 = (int)xc, y0 = (int)yc;
    int x1 = min(x0 + 1, W_ - 1), y1 = min(y0 + 1, H_ - 1);
    float wx = xc - (float)x0, wy = yc - (float)y0;
    float w00 = (1.f - wx) * (1.f - wy), w01 = wx * (1.f - wy);
    float w10 = (1.f - wx) * wy,         w11 = wx * wy;
    size_t i00 = (size_t)y0 * W_ + x0, i01 = (size_t)y0 * W_ + x1;
    size_t i10 = (size_t)y1 * W_ + x0, i11 = (size_t)y1 * W_ + x1;

#pragma unroll
    for (int c = 0; c < 3; c++) {
        const float* plane = img + ((size_t)b * 3 + c) * HW_;
        float v = __ldg(plane + i00) * w00 + __ldg(plane + i01) * w01
                + __ldg(plane + i10) * w10 + __ldg(plane + i11) * w11;
        v = fminf(fmaxf(v, 0.f), 1.f);
        out[((size_t)b * 3 + c) * HW_ + (size_t)i * W_ + j] = v;
    }
}

// ---------------------------------------------------------------------------
extern "C" void kernel_launch(void* const* d_in, const int* in_sizes, int n_in,
                              void* d_out, int out_size) {
    const float* img = (const float*)d_in[0];
    float* out = (float*)d_out;

    dim3 blk(32, 8, 1);
    dim3 gridS((SW_ + 31) / 32, (SH_ + 7) / 8, B_);
    dim3 gridF((W_  + 31) / 32, (H_  + 7) / 8, B_);

    k_luma_half  <<<gridS, blk>>>(img);
    k_sobel_edge <<<gridS, blk>>>();
    k_blur_h     <<<gridS, blk>>>();
    k_blur_v     <<<gridS, blk>>>();
    k_sobel_grad <<<gridS, blk>>>();
    k_resize_grad<<<gridF, blk>>>();
    k_warp       <<<gridF, blk>>>(img, out);
}

// round 3
// speedup vs baseline: 1.1332x; 1.1332x over previous
#include <cuda_runtime.h>
#include <math.h>

// Problem constants
#define B_   2
#define H_   1080
#define W_   1920
#define SH_  540
#define SW_  960
#define HW_  (H_*W_)
#define SHW_ (SH_*SW_)

// Scratch (device globals — no allocations allowed)
__device__ float  g_luma[B_*SHW_];
__device__ float  g_edge[B_*SHW_];
__device__ float  g_tmp [B_*SHW_];
__device__ float2 g_grad_half[B_*SHW_];

// ---------------------------------------------------------------------------
// helpers
// ---------------------------------------------------------------------------
__device__ __forceinline__ float sampX(const float* __restrict__ p, int W, int r, float x) {
    x = fminf(fmaxf(x, 0.f), (float)(W - 1));
    int x0 = (int)x;
    int x1 = min(x0 + 1, W - 1);
    float w = x - (float)x0;
    const float* row = p + (size_t)r * W;
    float a = __ldg(row + x0);
    float b = __ldg(row + x1);
    return a + (b - a) * w;
}

__device__ __forceinline__ float2 sxyRow(const float* __restrict__ p, int W, int r, int j, float sx) {
    float left  = sampX(p, W, r, (float)j - sx);
    float right = sampX(p, W, r, (float)j + sx);
    float c     = __ldg(p + (size_t)r * W + j);
    return make_float2(right - left, left + 2.f * c + right);
}

__device__ __forceinline__ float2 sxyAt(const float* __restrict__ p, int H, int W, float y, int j, float sx) {
    y = fminf(fmaxf(y, 0.f), (float)(H - 1));
    int r0 = (int)y;
    int r1 = min(r0 + 1, H - 1);
    float w = y - (float)r0;
    float2 a = sxyRow(p, W, r0, j, sx);
    float2 b = sxyRow(p, W, r1, j, sx);
    return make_float2(a.x + (b.x - a.x) * w, a.y + (b.y - a.y) * w);
}

// ---------------------------------------------------------------------------
// k1: luma + downsample 1080x1920 -> 540x960 (align_corners)
// ---------------------------------------------------------------------------
__global__ void __launch_bounds__(256) k_luma_half(const float* __restrict__ img) {
    int j = blockIdx.x * 32 + threadIdx.x;
    int i = blockIdx.y * 8  + threadIdx.y;
    int b = blockIdx.z;
    if (j >= SW_ || i >= SH_) return;

    float ys = fminf((float)i * (1079.0f / 539.0f), 1079.0f);
    float xs = fminf((float)j * (1919.0f / 959.0f), 1919.0f);
    int y0 = (int)ys, x0 = (int)xs;
    int y1 = min(y0 + 1, H_ - 1), x1 = min(x0 + 1, W_ - 1);
    float wy = ys - (float)y0, wx = xs - (float)x0;

    const float* r0c = img + (size_t)b * 3 * HW_;
    const float* g0c = r0c + HW_;
    const float* b0c = r0c + 2 * HW_;

    int i00 = y0 * W_ + x0, i01 = y0 * W_ + x1, i10 = y1 * W_ + x0, i11 = y1 * W_ + x1;
    float v00 = 0.299f*__ldg(r0c+i00) + 0.587f*__ldg(g0c+i00) + 0.114f*__ldg(b0c+i00);
    float v01 = 0.299f*__ldg(r0c+i01) + 0.587f*__ldg(g0c+i01) + 0.114f*__ldg(b0c+i01);
    float v10 = 0.299f*__ldg(r0c+i10) + 0.587f*__ldg(g0c+i10) + 0.114f*__ldg(b0c+i10);
    float v11 = 0.299f*__ldg(r0c+i11) + 0.587f*__ldg(g0c+i11) + 0.114f*__ldg(b0c+i11);

    float v = (v00 * (1.f - wx) + v01 * wx) * (1.f - wy)
            + (v10 * (1.f - wx) + v11 * wx) * wy;
    g_luma[(size_t)b * SHW_ + i * SW_ + j] = v;
}

// ---------------------------------------------------------------------------
// k2: fused sobel_x + sobel_y (offset 1.0) -> edge magnitude
// ---------------------------------------------------------------------------
__global__ void __launch_bounds__(256) k_sobel_edge() {
    int j = blockIdx.x * 32 + threadIdx.x;
    int i = blockIdx.y * 8  + threadIdx.y;
    int b = blockIdx.z;
    if (j >= SW_ || i >= SH_) return;

    const float sx = 1.0f * (float)(SW_ - 1) / (float)SW_;
    const float sy = 1.0f * (float)(SH_ - 1) / (float)SH_;
    const float* p = g_luma + (size_t)b * SHW_;

    float2 top = sxyAt (p, SH_, SW_, (float)i - sy, j, sx);
    float2 mid = sxyRow(p, SW_, i, j, sx);
    float2 bot = sxyAt (p, SH_, SW_, (float)i + sy, j, sx);

    float xg = (top.x + 2.f * mid.x + bot.x) * 0.125f;
    float yg = (bot.y - top.y) * 0.125f;
    float mag = sqrtf(xg * xg + yg * yg);
    g_edge[(size_t)b * SHW_ + i * SW_ + j] = powf(mag, 0.7f);
}

// ---------------------------------------------------------------------------
// k3: fused separable 5-tap gaussian (sigma=1, replicate padding), smem tile
//     reads g_edge, writes g_tmp.  NOTE: output store is bounds-guarded
//     (540 % 8 != 0 -> last row-block has 4 invalid rows).
// ---------------------------------------------------------------------------
#define GW0 0.4026199469f
#define GW1 0.2442013420f
#define GW2 0.0544886845f

__global__ void __launch_bounds__(256) k_blur() {
    __shared__ float sA[12][36];   // input tile with 2px halo each side
    __shared__ float sB[12][32];   // horizontally blurred (vertical halo kept)

    int j0 = blockIdx.x * 32;
    int i0 = blockIdx.y * 8;
    int b  = blockIdx.z;
    int tx = threadIdx.x, ty = threadIdx.y;
    int tid = ty * 32 + tx;

    const float* p = g_edge + (size_t)b * SHW_;

    // load 12x36 input tile (clamped)
    for (int t = tid; t < 12 * 36; t += 256) {
        int r = t / 36, c = t % 36;
        int gi = min(max(i0 - 2 + r, 0), SH_ - 1);
        int gj = min(max(j0 - 2 + c, 0), SW_ - 1);
        sA[r][c] = __ldg(p + (size_t)gi * SW_ + gj);
    }
    __syncthreads();

    // horizontal pass: 12 rows x 32 cols
    for (int t = tid; t < 12 * 32; t += 256) {
        int r = t / 32, c = t % 32;
        sB[r][c] = GW2 * (sA[r][c] + sA[r][c + 4])
                 + GW1 * (sA[r][c + 1] + sA[r][c + 3])
                 + GW0 * sA[r][c + 2];
    }
    __syncthreads();

    // vertical pass: output row ty uses sB rows ty..ty+4
    int i = i0 + ty, j = j0 + tx;
    if (i < SH_ && j < SW_) {
        float v = GW2 * (sB[ty][tx] + sB[ty + 4][tx])
                + GW1 * (sB[ty + 1][tx] + sB[ty + 3][tx])
                + GW0 * sB[ty + 2][tx];
        g_tmp[(size_t)b * SHW_ + (size_t)i * SW_ + j] = v;
    }
}

// ---------------------------------------------------------------------------
// k4: fused sobel pair (offset 0.5) on blurred edge -> grad_field half
//     reads g_tmp, writes g_grad_half
// ---------------------------------------------------------------------------
__global__ void __launch_bounds__(256) k_sobel_grad() {
    int j = blockIdx.x * 32 + threadIdx.x;
    int i = blockIdx.y * 8  + threadIdx.y;
    int b = blockIdx.z;
    if (j >= SW_ || i >= SH_) return;

    const float sx = 0.5f * (float)(SW_ - 1) / (float)SW_;
    const float sy = 0.5f * (float)(SH_ - 1) / (float)SH_;
    const float* p = g_tmp + (size_t)b * SHW_;

    float2 top = sxyAt (p, SH_, SW_, (float)i - sy, j, sx);
    float2 mid = sxyRow(p, SW_, i, j, sx);
    float2 bot = sxyAt (p, SH_, SW_, (float)i + sy, j, sx);

    float xg = (top.x + 2.f * mid.x + bot.x) * 0.125f;
    float yg = (bot.y - top.y) * 0.125f;
    g_grad_half[(size_t)b * SHW_ + i * SW_ + j] = make_float2(xg, yg);
}

// ---------------------------------------------------------------------------
// k5: fused resize + iterative warp + final image sample + clip
//
// Positions drift < 0.6 px (6 iters x 0.1 px), so a 32x8 output tile samples
// the full-res grad field only on the 34x11 lattice patch
// [j0-1, j0+32] x [i0-1, i0+9]. Compute those lattice values exactly as the
// standalone resize did (half-res -> full-res bilinear), keep them in smem,
// iterate from smem.
// ---------------------------------------------------------------------------
#define SMW 34
#define SMH 11

__global__ void __launch_bounds__(256) k_warp_fused(const float* __restrict__ img,
                                                    float* __restrict__ out) {
    __shared__ float2 sg[SMH][SMW];

    int j0 = blockIdx.x * 32;
    int i0 = blockIdx.y * 8;
    int b  = blockIdx.z;
    int tx = threadIdx.x, ty = threadIdx.y;
    int tid = ty * 32 + tx;

    const float2* gh = g_grad_half + (size_t)b * SHW_;

    // fill full-res grad lattice patch (exact resize math)
    for (int t = tid; t < SMW * SMH; t += 256) {
        int sy = t / SMW, sx = t % SMW;
        int I = min(max(i0 - 1 + sy, 0), H_ - 1);
        int J = min(max(j0 - 1 + sx, 0), W_ - 1);

        float ys = fminf((float)I * (539.0f / 1079.0f), (float)(SH_ - 1));
        float xs = fminf((float)J * (959.0f / 1919.0f), (float)(SW_ - 1));
        int y0 = (int)ys, x0 = (int)xs;
        int y1 = min(y0 + 1, SH_ - 1), x1 = min(x0 + 1, SW_ - 1);
        float wy = ys - (float)y0, wx = xs - (float)x0;

        float2 v00 = __ldg(&gh[(size_t)y0 * SW_ + x0]);
        float2 v01 = __ldg(&gh[(size_t)y0 * SW_ + x1]);
        float2 v10 = __ldg(&gh[(size_t)y1 * SW_ + x0]);
        float2 v11 = __ldg(&gh[(size_t)y1 * SW_ + x1]);
        float2 r;
        r.x = (v00.x * (1.f - wx) + v01.x * wx) * (1.f - wy)
            + (v10.x * (1.f - wx) + v11.x * wx) * wy;
        r.y = (v00.y * (1.f - wx) + v01.y * wx) * (1.f - wy)
            + (v10.y * (1.f - wx) + v11.y * wx) * wy;
        sg[sy][sx] = r;
    }
    __syncthreads();

    int j = j0 + tx, i = i0 + ty;   // grid divides exactly (1920/32, 1080/8)

    const float stx = 0.1f * (float)(W_ - 1) / (float)W_;
    const float sty = 0.1f * (float)(H_ - 1) / (float)H_;

    float px = (float)j, py = (float)i;
#pragma unroll
    for (int it = 0; it < 6; it++) {
        float xc = fminf(fmaxf(px, 0.f), (float)(W_ - 1));
        float yc = fminf(fmaxf(py, 0.f), (float)(H_ - 1));
        int x0 = (int)xc, y0 = (int)yc;
        float wx = xc - (float)x0, wy = yc - (float)y0;
        int sx0 = x0 - (j0 - 1);
        int sy0 = y0 - (i0 - 1);
        float2 v00 = sg[sy0][sx0];
        float2 v01 = sg[sy0][sx0 + 1];
        float2 v10 = sg[sy0 + 1][sx0];
        float2 v11 = sg[sy0 + 1][sx0 + 1];
        float dx = (v00.x * (1.f - wx) + v01.x * wx) * (1.f - wy)
                 + (v10.x * (1.f - wx) + v11.x * wx) * wy;
        float dy = (v00.y * (1.f - wx) + v01.y * wx) * (1.f - wy)
                 + (v10.y * (1.f - wx) + v11.y * wx) * wy;
        float inv = 1.f / (sqrtf(dx * dx + dy * dy) + 0.01f);
        px -= dx * inv * stx;
        py -= dy * inv * sty;
    }

    // final image sample (3 channels) + clip
    float xc = fminf(fmaxf(px, 0.f), (float)(W_ - 1));
    float yc = fminf(fmaxf(py, 0.f), (float)(H_ - 1));
    int x0 = (int)xc, y0 = (int)yc;
    int x1 = min(x0 + 1, W_ - 1), y1 = min(y0 + 1, H_ - 1);
    float wx = xc - (float)x0, wy = yc - (float)y0;
    float w00 = (1.f - wx) * (1.f - wy), w01 = wx * (1.f - wy);
    float w10 = (1.f - wx) * wy,         w11 = wx * wy;
    size_t i00 = (size_t)y0 * W_ + x0, i01 = (size_t)y0 * W_ + x1;
    size_t i10 = (size_t)y1 * W_ + x0, i11 = (size_t)y1 * W_ + x1;

#pragma unroll
    for (int c = 0; c < 3; c++) {
        const float* plane = img + ((size_t)b * 3 + c) * HW_;
        float v = __ldg(plane + i00) * w00 + __ldg(plane + i01) * w01
                + __ldg(plane + i10) * w10 + __ldg(plane + i11) * w11;
        v = fminf(fmaxf(v, 0.f), 1.f);
        out[((size_t)b * 3 + c) * HW_ + (size_t)i * W_ + j] = v;
    }
}

// ---------------------------------------------------------------------------
extern "C" void kernel_launch(void* const* d_in, const int* in_sizes, int n_in,
                              void* d_out, int out_size) {
    const float* img = (const float*)d_in[0];
    float* out = (float*)d_out;

    dim3 blk(32, 8, 1);
    dim3 gridS((SW_ + 31) / 32, (SH_ + 7) / 8, B_);
    dim3 gridF(W_ / 32, H_ / 8, B_);

    k_luma_half  <<<gridS, blk>>>(img);
    k_sobel_edge <<<gridS, blk>>>();
    k_blur       <<<gridS, blk>>>();
    k_sobel_grad <<<gridS, blk>>>();
    k_warp_fused <<<gridF, blk>>>(img, out);
}

// round 4
// speedup vs baseline: 1.2642x; 1.1156x over previous
#include <cuda_runtime.h>
#include <math.h>

// Problem constants
#define B_   2
#define H_   1080
#define W_   1920
#define SH_  540
#define SW_  960
#define HW_  (H_*W_)
#define SHW_ (SH_*SW_)

// Scratch (device globals — no allocations allowed)
__device__ float  g_luma[B_*SHW_];
__device__ float2 g_grad_half[B_*SHW_];

// constant-shift sobel weights (shift = offset*(N-1)/N, always < 1)
#define SXE ((float)(SW_-1)/(float)SW_)        // edge sobel, offset 1.0
#define SYE ((float)(SH_-1)/(float)SH_)
#define SXG (0.5f*(float)(SW_-1)/(float)SW_)   // grad sobel, offset 0.5
#define SYG (0.5f*(float)(SH_-1)/(float)SH_)

// gaussian sigma=1 5-tap
#define GW0 0.4026199469f
#define GW1 0.2442013420f
#define GW2 0.0544886845f

__device__ __forceinline__ int iclamp(int v, int lo, int hi) {
    return min(max(v, lo), hi);
}

// ---------------------------------------------------------------------------
// k1: luma + downsample 1080x1920 -> 540x960 (align_corners)
// ---------------------------------------------------------------------------
__global__ void __launch_bounds__(256) k_luma_half(const float* __restrict__ img) {
    int j = blockIdx.x * 32 + threadIdx.x;
    int i = blockIdx.y * 8  + threadIdx.y;
    int b = blockIdx.z;
    if (j >= SW_ || i >= SH_) return;

    float ys = fminf((float)i * (1079.0f / 539.0f), 1079.0f);
    float xs = fminf((float)j * (1919.0f / 959.0f), 1919.0f);
    int y0 = (int)ys, x0 = (int)xs;
    int y1 = min(y0 + 1, H_ - 1), x1 = min(x0 + 1, W_ - 1);
    float wy = ys - (float)y0, wx = xs - (float)x0;

    const float* r0c = img + (size_t)b * 3 * HW_;
    const float* g0c = r0c + HW_;
    const float* b0c = r0c + 2 * HW_;

    int i00 = y0 * W_ + x0, i01 = y0 * W_ + x1, i10 = y1 * W_ + x0, i11 = y1 * W_ + x1;
    float v00 = 0.299f*__ldg(r0c+i00) + 0.587f*__ldg(g0c+i00) + 0.114f*__ldg(b0c+i00);
    float v01 = 0.299f*__ldg(r0c+i01) + 0.587f*__ldg(g0c+i01) + 0.114f*__ldg(b0c+i01);
    float v10 = 0.299f*__ldg(r0c+i10) + 0.587f*__ldg(g0c+i10) + 0.114f*__ldg(b0c+i10);
    float v11 = 0.299f*__ldg(r0c+i11) + 0.587f*__ldg(g0c+i11) + 0.114f*__ldg(b0c+i11);

    float v = (v00 * (1.f - wx) + v01 * wx) * (1.f - wy)
            + (v10 * (1.f - wx) + v11 * wx) * wy;
    g_luma[(size_t)b * SHW_ + i * SW_ + j] = v;
}

// ---------------------------------------------------------------------------
// k2: fully fused field kernel: luma -> edge sobel -> gaussian -> grad sobel
//     All stages are constant-weight clamped 3x3 / 5-tap stencils.
//     Tile chain for a 32x8 output tile:
//       luma  40x16  (halo 4)   rows [i0-4, i0+11], cols [j0-4, j0+35]
//       edge  38x14  (halo 3)   rows [i0-3, i0+10], cols [j0-3, j0+34]
//       blurH 34x14             rows [i0-3, i0+10], cols [j0-1, j0+32]
//       blurV 34x10             rows [i0-1, i0+8 ], cols [j0-1, j0+32]
//       grad  32x8
//     Out-of-image slots hold the value at the clamped coordinate, which
//     reproduces border-replicate semantics of every stage exactly.
// ---------------------------------------------------------------------------
__global__ void __launch_bounds__(256) k_field() {
    __shared__ float sL[16][41];
    __shared__ float sE[14][39];
    __shared__ float sH[14][35];
    __shared__ float sV[10][35];

    int j0 = blockIdx.x * 32;
    int i0 = blockIdx.y * 8;
    int b  = blockIdx.z;
    int tx = threadIdx.x, ty = threadIdx.y;
    int tid = ty * 32 + tx;

    const float* lp = g_luma + (size_t)b * SHW_;

    // ---- load luma tile 16x40 (clamped) ----
    for (int t = tid; t < 16 * 40; t += 256) {
        int r = t / 40, c = t % 40;
        int gi = iclamp(i0 - 4 + r, 0, SH_ - 1);
        int gj = iclamp(j0 - 4 + c, 0, SW_ - 1);
        sL[r][c] = __ldg(lp + (size_t)gi * SW_ + gj);
    }
    __syncthreads();

    // ---- edge sobel (offset 1.0) + magnitude^0.7 : 14x38 ----
    for (int t = tid; t < 14 * 38; t += 256) {
        int er = t / 38, ec = t % 38;
        int ci = iclamp(i0 - 3 + er, 0, SH_ - 1);
        int cj = iclamp(j0 - 3 + ec, 0, SW_ - 1);
        int rm = max(ci - 1, 0)        - (i0 - 4);
        int rc = ci                    - (i0 - 4);
        int rp = min(ci + 1, SH_ - 1)  - (i0 - 4);
        int cm = max(cj - 1, 0)        - (j0 - 4);
        int cc = cj                    - (j0 - 4);
        int cp = min(cj + 1, SW_ - 1)  - (j0 - 4);

        float gxm = SXE * (sL[rm][cp] - sL[rm][cm]);
        float gxc = SXE * (sL[rc][cp] - sL[rc][cm]);
        float gxp = SXE * (sL[rp][cp] - sL[rp][cm]);
        float gsm = SXE * (sL[rm][cm] + sL[rm][cp]) + (4.f - 2.f * SXE) * sL[rm][cc];
        float gsp = SXE * (sL[rp][cm] + sL[rp][cp]) + (4.f - 2.f * SXE) * sL[rp][cc];

        float xg = 0.125f * (SYE * (gxm + gxp) + (4.f - 2.f * SYE) * gxc);
        float yg = 0.125f * SYE * (gsp - gsm);
        float m2 = xg * xg + yg * yg;
        sE[er][ec] = exp2f(0.35f * __log2f(m2));   // (m2)^0.35 == mag^0.7
    }
    __syncthreads();

    // ---- horizontal gaussian: 14x34 ----
    for (int t = tid; t < 14 * 34; t += 256) {
        int hr = t / 34, hc = t % 34;
        int cj = iclamp(j0 - 1 + hc, 0, SW_ - 1);
        int c0 = max(cj - 2, 0)       - (j0 - 3);
        int c1 = max(cj - 1, 0)       - (j0 - 3);
        int c2 = cj                   - (j0 - 3);
        int c3 = min(cj + 1, SW_ - 1) - (j0 - 3);
        int c4 = min(cj + 2, SW_ - 1) - (j0 - 3);
        sH[hr][hc] = GW2 * (sE[hr][c0] + sE[hr][c4])
                   + GW1 * (sE[hr][c1] + sE[hr][c3])
                   + GW0 * sE[hr][c2];
    }
    __syncthreads();

    // ---- vertical gaussian: 10x34 ----
    for (int t = tid; t < 10 * 34; t += 256) {
        int vr = t / 34, hc = t % 34;
        int ci = iclamp(i0 - 1 + vr, 0, SH_ - 1);
        int r0 = max(ci - 2, 0)       - (i0 - 3);
        int r1 = max(ci - 1, 0)       - (i0 - 3);
        int r2 = ci                   - (i0 - 3);
        int r3 = min(ci + 1, SH_ - 1) - (i0 - 3);
        int r4 = min(ci + 2, SH_ - 1) - (i0 - 3);
        sV[vr][hc] = GW2 * (sH[r0][hc] + sH[r4][hc])
                   + GW1 * (sH[r1][hc] + sH[r3][hc])
                   + GW0 * sH[r2][hc];
    }
    __syncthreads();

    // ---- grad sobel (offset 0.5): 32x8, one per thread ----
    int i = i0 + ty, j = j0 + tx;
    if (i < SH_ && j < SW_) {
        int rm = max(i - 1, 0)        - (i0 - 1);
        int rc = i                    - (i0 - 1);
        int rp = min(i + 1, SH_ - 1)  - (i0 - 1);
        int cm = max(j - 1, 0)        - (j0 - 1);
        int cc = j                    - (j0 - 1);
        int cp = min(j + 1, SW_ - 1)  - (j0 - 1);

        float gxm = SXG * (sV[rm][cp] - sV[rm][cm]);
        float gxc = SXG * (sV[rc][cp] - sV[rc][cm]);
        float gxp = SXG * (sV[rp][cp] - sV[rp][cm]);
        float gsm = SXG * (sV[rm][cm] + sV[rm][cp]) + (4.f - 2.f * SXG) * sV[rm][cc];
        float gsp = SXG * (sV[rp][cm] + sV[rp][cp]) + (4.f - 2.f * SXG) * sV[rp][cc];

        float xg = 0.125f * (SYG * (gxm + gxp) + (4.f - 2.f * SYG) * gxc);
        float yg = 0.125f * SYG * (gsp - gsm);
        g_grad_half[(size_t)b * SHW_ + (size_t)i * SW_ + j] = make_float2(xg, yg);
    }
}

// ---------------------------------------------------------------------------
// k3: fused resize + iterative warp + final image sample + clip
// ---------------------------------------------------------------------------
#define SMW 34
#define SMH 11

__global__ void __launch_bounds__(256) k_warp_fused(const float* __restrict__ img,
                                                    float* __restrict__ out) {
    __shared__ float2 sg[SMH][SMW];

    int j0 = blockIdx.x * 32;
    int i0 = blockIdx.y * 8;
    int b  = blockIdx.z;
    int tx = threadIdx.x, ty = threadIdx.y;
    int tid = ty * 32 + tx;

    const float2* gh = g_grad_half + (size_t)b * SHW_;

    // fill full-res grad lattice patch (exact resize math)
    for (int t = tid; t < SMW * SMH; t += 256) {
        int sy = t / SMW, sx = t % SMW;
        int I = iclamp(i0 - 1 + sy, 0, H_ - 1);
        int J = iclamp(j0 - 1 + sx, 0, W_ - 1);

        float ys = fminf((float)I * (539.0f / 1079.0f), (float)(SH_ - 1));
        float xs = fminf((float)J * (959.0f / 1919.0f), (float)(SW_ - 1));
        int y0 = (int)ys, x0 = (int)xs;
        int y1 = min(y0 + 1, SH_ - 1), x1 = min(x0 + 1, SW_ - 1);
        float wy = ys - (float)y0, wx = xs - (float)x0;

        float2 v00 = __ldg(&gh[(size_t)y0 * SW_ + x0]);
        float2 v01 = __ldg(&gh[(size_t)y0 * SW_ + x1]);
        float2 v10 = __ldg(&gh[(size_t)y1 * SW_ + x0]);
        float2 v11 = __ldg(&gh[(size_t)y1 * SW_ + x1]);
        float2 r;
        r.x = (v00.x * (1.f - wx) + v01.x * wx) * (1.f - wy)
            + (v10.x * (1.f - wx) + v11.x * wx) * wy;
        r.y = (v00.y * (1.f - wx) + v01.y * wx) * (1.f - wy)
            + (v10.y * (1.f - wx) + v11.y * wx) * wy;
        sg[sy][sx] = r;
    }
    __syncthreads();

    int j = j0 + tx, i = i0 + ty;

    const float stx = 0.1f * (float)(W_ - 1) / (float)W_;
    const float sty = 0.1f * (float)(H_ - 1) / (float)H_;

    float px = (float)j, py = (float)i;
#pragma unroll
    for (int it = 0; it < 6; it++) {
        float xc = fminf(fmaxf(px, 0.f), (float)(W_ - 1));
        float yc = fminf(fmaxf(py, 0.f), (float)(H_ - 1));
        int x0 = (int)xc, y0 = (int)yc;
        float wx = xc - (float)x0, wy = yc - (float)y0;
        int sx0 = x0 - (j0 - 1);
        int sy0 = y0 - (i0 - 1);
        float2 v00 = sg[sy0][sx0];
        float2 v01 = sg[sy0][sx0 + 1];
        float2 v10 = sg[sy0 + 1][sx0];
        float2 v11 = sg[sy0 + 1][sx0 + 1];
        float dx = (v00.x * (1.f - wx) + v01.x * wx) * (1.f - wy)
                 + (v10.x * (1.f - wx) + v11.x * wx) * wy;
        float dy = (v00.y * (1.f - wx) + v01.y * wx) * (1.f - wy)
                 + (v10.y * (1.f - wx) + v11.y * wx) * wy;
        float inv = 1.f / (sqrtf(dx * dx + dy * dy) + 0.01f);
        px -= dx * inv * stx;
        py -= dy * inv * sty;
    }

    // final image sample (3 channels) + clip
    float xc = fminf(fmaxf(px, 0.f), (float)(W_ - 1));
    float yc = fminf(fmaxf(py, 0.f), (float)(H_ - 1));
    int x0 = (int)xc, y0 = (int)yc;
    int x1 = min(x0 + 1, W_ - 1), y1 = min(y0 + 1, H_ - 1);
    float wx = xc - (float)x0, wy = yc - (float)y0;
    float w00 = (1.f - wx) * (1.f - wy), w01 = wx * (1.f - wy);
    float w10 = (1.f - wx) * wy,         w11 = wx * wy;
    size_t i00 = (size_t)y0 * W_ + x0, i01 = (size_t)y0 * W_ + x1;
    size_t i10 = (size_t)y1 * W_ + x0, i11 = (size_t)y1 * W_ + x1;

#pragma unroll
    for (int c = 0; c < 3; c++) {
        const float* plane = img + ((size_t)b * 3 + c) * HW_;
        float v = __ldg(plane + i00) * w00 + __ldg(plane + i01) * w01
                + __ldg(plane + i10) * w10 + __ldg(plane + i11) * w11;
        v = fminf(fmaxf(v, 0.f), 1.f);
        out[((size_t)b * 3 + c) * HW_ + (size_t)i * W_ + j] = v;
    }
}

// ---------------------------------------------------------------------------
extern "C" void kernel_launch(void* const* d_in, const int* in_sizes, int n_in,
                              void* d_out, int out_size) {
    const float* img = (const float*)d_in[0];
    float* out = (float*)d_out;

    dim3 blk(32, 8, 1);
    dim3 gridS((SW_ + 31) / 32, (SH_ + 7) / 8, B_);
    dim3 gridF(W_ / 32, H_ / 8, B_);

    k_luma_half <<<gridS, blk>>>(img);
    k_field     <<<gridS, blk>>>();
    k_warp_fused<<<gridF, blk>>>(img, out);
}

// round 5
// speedup vs baseline: 1.3673x; 1.0816x over previous
#include <cuda_runtime.h>
#include <math.h>

// Problem constants
#define B_   2
#define H_   1080
#define W_   1920
#define SH_  540
#define SW_  960
#define HW_  (H_*W_)
#define SHW_ (SH_*SW_)

// Scratch (device globals — no allocations allowed)
__device__ float  g_luma[B_*SHW_];
__device__ float2 g_grad_half[B_*SHW_];

// constant-shift sobel weights (shift = offset*(N-1)/N, always < 1)
#define SXE ((float)(SW_-1)/(float)SW_)        // edge sobel, offset 1.0
#define SYE ((float)(SH_-1)/(float)SH_)
#define SXG (0.5f*(float)(SW_-1)/(float)SW_)   // grad sobel, offset 0.5
#define SYG (0.5f*(float)(SH_-1)/(float)SH_)

// gaussian sigma=1 5-tap
#define GW0 0.4026199469f
#define GW1 0.2442013420f
#define GW2 0.0544886845f

__device__ __forceinline__ int iclamp(int v, int lo, int hi) {
    return min(max(v, lo), hi);
}

// ---------------------------------------------------------------------------
// k1: luma + downsample 1080x1920 -> 540x960 (align_corners)
// ---------------------------------------------------------------------------
__global__ void __launch_bounds__(256) k_luma_half(const float* __restrict__ img) {
    int j = blockIdx.x * 32 + threadIdx.x;
    int i = blockIdx.y * 8  + threadIdx.y;
    int b = blockIdx.z;
    if (j >= SW_ || i >= SH_) return;

    float ys = fminf((float)i * (1079.0f / 539.0f), 1079.0f);
    float xs = fminf((float)j * (1919.0f / 959.0f), 1919.0f);
    int y0 = (int)ys, x0 = (int)xs;
    int y1 = min(y0 + 1, H_ - 1), x1 = min(x0 + 1, W_ - 1);
    float wy = ys - (float)y0, wx = xs - (float)x0;

    const float* r0c = img + (size_t)b * 3 * HW_;
    const float* g0c = r0c + HW_;
    const float* b0c = r0c + 2 * HW_;

    int i00 = y0 * W_ + x0, i01 = y0 * W_ + x1, i10 = y1 * W_ + x0, i11 = y1 * W_ + x1;
    float v00 = 0.299f*__ldg(r0c+i00) + 0.587f*__ldg(g0c+i00) + 0.114f*__ldg(b0c+i00);
    float v01 = 0.299f*__ldg(r0c+i01) + 0.587f*__ldg(g0c+i01) + 0.114f*__ldg(b0c+i01);
    float v10 = 0.299f*__ldg(r0c+i10) + 0.587f*__ldg(g0c+i10) + 0.114f*__ldg(b0c+i10);
    float v11 = 0.299f*__ldg(r0c+i11) + 0.587f*__ldg(g0c+i11) + 0.114f*__ldg(b0c+i11);

    float v = (v00 * (1.f - wx) + v01 * wx) * (1.f - wy)
            + (v10 * (1.f - wx) + v11 * wx) * wy;
    g_luma[(size_t)b * SHW_ + i * SW_ + j] = v;
}

// ---------------------------------------------------------------------------
// k2: fused field kernel on 32x32 tiles (4 outputs/thread):
//     luma tile -> edge sobel -> gaussian H -> gaussian V -> grad sobel
//     Tile chain:
//       luma  40x40 (rows/cols [x0-4, x0+35])
//       edge  38x38 (rows/cols [x0-3, x0+34])
//       blurH 38x34 (rows [i0-3,i0+34], cols [j0-1,j0+32])
//       blurV 34x34 (rows [i0-1,i0+32])
//       grad  32x32
// ---------------------------------------------------------------------------
__global__ void __launch_bounds__(256) k_field() {
    __shared__ float sL[40][41];
    __shared__ float sE[38][39];
    __shared__ float sH[38][35];
    __shared__ float sV[34][35];

    int j0 = blockIdx.x * 32;
    int i0 = blockIdx.y * 32;
    int b  = blockIdx.z;
    int tid = threadIdx.y * 32 + threadIdx.x;

    const float* lp = g_luma + (size_t)b * SHW_;

    // ---- load luma tile 40x40 (clamped) ----
    for (int t = tid; t < 40 * 40; t += 256) {
        int r = t / 40, c = t % 40;
        int gi = iclamp(i0 - 4 + r, 0, SH_ - 1);
        int gj = iclamp(j0 - 4 + c, 0, SW_ - 1);
        sL[r][c] = __ldg(lp + (size_t)gi * SW_ + gj);
    }
    __syncthreads();

    // ---- edge sobel (offset 1.0) + magnitude^0.7 : 38x38 ----
    for (int t = tid; t < 38 * 38; t += 256) {
        int er = t / 38, ec = t % 38;
        int ci = iclamp(i0 - 3 + er, 0, SH_ - 1);
        int cj = iclamp(j0 - 3 + ec, 0, SW_ - 1);
        int rm = max(ci - 1, 0)        - (i0 - 4);
        int rc = ci                    - (i0 - 4);
        int rp = min(ci + 1, SH_ - 1)  - (i0 - 4);
        int cm = max(cj - 1, 0)        - (j0 - 4);
        int cc = cj                    - (j0 - 4);
        int cp = min(cj + 1, SW_ - 1)  - (j0 - 4);

        float gxm = SXE * (sL[rm][cp] - sL[rm][cm]);
        float gxc = SXE * (sL[rc][cp] - sL[rc][cm]);
        float gxp = SXE * (sL[rp][cp] - sL[rp][cm]);
        float gsm = SXE * (sL[rm][cm] + sL[rm][cp]) + (4.f - 2.f * SXE) * sL[rm][cc];
        float gsp = SXE * (sL[rp][cm] + sL[rp][cp]) + (4.f - 2.f * SXE) * sL[rp][cc];

        float xg = 0.125f * (SYE * (gxm + gxp) + (4.f - 2.f * SYE) * gxc);
        float yg = 0.125f * SYE * (gsp - gsm);
        float m2 = xg * xg + yg * yg;
        sE[er][ec] = exp2f(0.35f * __log2f(m2));   // (m2)^0.35 == mag^0.7
    }
    __syncthreads();

    // ---- horizontal gaussian: 38x34 ----
    for (int t = tid; t < 38 * 34; t += 256) {
        int hr = t / 34, hc = t % 34;
        int cj = iclamp(j0 - 1 + hc, 0, SW_ - 1);
        int c0 = max(cj - 2, 0)       - (j0 - 3);
        int c1 = max(cj - 1, 0)       - (j0 - 3);
        int c2 = cj                   - (j0 - 3);
        int c3 = min(cj + 1, SW_ - 1) - (j0 - 3);
        int c4 = min(cj + 2, SW_ - 1) - (j0 - 3);
        sH[hr][hc] = GW2 * (sE[hr][c0] + sE[hr][c4])
                   + GW1 * (sE[hr][c1] + sE[hr][c3])
                   + GW0 * sE[hr][c2];
    }
    __syncthreads();

    // ---- vertical gaussian: 34x34 ----
    for (int t = tid; t < 34 * 34; t += 256) {
        int vr = t / 34, hc = t % 34;
        int ci = iclamp(i0 - 1 + vr, 0, SH_ - 1);
        int r0 = max(ci - 2, 0)       - (i0 - 3);
        int r1 = max(ci - 1, 0)       - (i0 - 3);
        int r2 = ci                   - (i0 - 3);
        int r3 = min(ci + 1, SH_ - 1) - (i0 - 3);
        int r4 = min(ci + 2, SH_ - 1) - (i0 - 3);
        sV[vr][hc] = GW2 * (sH[r0][hc] + sH[r4][hc])
                   + GW1 * (sH[r1][hc] + sH[r3][hc])
                   + GW0 * sH[r2][hc];
    }
    __syncthreads();

    // ---- grad sobel (offset 0.5): 32x32, 4 per thread ----
    for (int t = tid; t < 32 * 32; t += 256) {
        int gr = t / 32, gc = t % 32;
        int i = i0 + gr, j = j0 + gc;
        if (i >= SH_ || j >= SW_) continue;
        int rm = max(i - 1, 0)        - (i0 - 1);
        int rc = i                    - (i0 - 1);
        int rp = min(i + 1, SH_ - 1)  - (i0 - 1);
        int cm = max(j - 1, 0)        - (j0 - 1);
        int cc = j                    - (j0 - 1);
        int cp = min(j + 1, SW_ - 1)  - (j0 - 1);

        float gxm = SXG * (sV[rm][cp] - sV[rm][cm]);
        float gxc = SXG * (sV[rc][cp] - sV[rc][cm]);
        float gxp = SXG * (sV[rp][cp] - sV[rp][cm]);
        float gsm = SXG * (sV[rm][cm] + sV[rm][cp]) + (4.f - 2.f * SXG) * sV[rm][cc];
        float gsp = SXG * (sV[rp][cm] + sV[rp][cp]) + (4.f - 2.f * SXG) * sV[rp][cc];

        float xg = 0.125f * (SYG * (gxm + gxp) + (4.f - 2.f * SYG) * gxc);
        float yg = 0.125f * SYG * (gsp - gsm);
        g_grad_half[(size_t)b * SHW_ + (size_t)i * SW_ + j] = make_float2(xg, yg);
    }
}

// ---------------------------------------------------------------------------
// k3: fused resize + iterative warp + final sample, 32x16 tile, 2 px/thread
//     (two independent iteration chains per thread -> 2x ILP on the
//      latency-bound warp loop)
// ---------------------------------------------------------------------------
#define SMW 34
#define SMH 18

__global__ void __launch_bounds__(256) k_warp_fused(const float* __restrict__ img,
                                                    float* __restrict__ out) {
    __shared__ float2 sg[SMH][SMW];

    int j0 = blockIdx.x * 32;
    int i0 = blockIdx.y * 16;
    int b  = blockIdx.z;
    int tx = threadIdx.x, ty = threadIdx.y;
    int tid = ty * 32 + tx;

    const float2* gh = g_grad_half + (size_t)b * SHW_;

    // fill full-res grad lattice patch [i0-1, i0+16] x [j0-1, j0+32]
    for (int t = tid; t < SMW * SMH; t += 256) {
        int sy = t / SMW, sx = t % SMW;
        int I = iclamp(i0 - 1 + sy, 0, H_ - 1);
        int J = iclamp(j0 - 1 + sx, 0, W_ - 1);

        float ys = fminf((float)I * (539.0f / 1079.0f), (float)(SH_ - 1));
        float xs = fminf((float)J * (959.0f / 1919.0f), (float)(SW_ - 1));
        int y0 = (int)ys, x0 = (int)xs;
        int y1 = min(y0 + 1, SH_ - 1), x1 = min(x0 + 1, SW_ - 1);
        float wy = ys - (float)y0, wx = xs - (float)x0;

        float2 v00 = __ldg(&gh[(size_t)y0 * SW_ + x0]);
        float2 v01 = __ldg(&gh[(size_t)y0 * SW_ + x1]);
        float2 v10 = __ldg(&gh[(size_t)y1 * SW_ + x0]);
        float2 v11 = __ldg(&gh[(size_t)y1 * SW_ + x1]);
        float2 r;
        r.x = (v00.x * (1.f - wx) + v01.x * wx) * (1.f - wy)
            + (v10.x * (1.f - wx) + v11.x * wx) * wy;
        r.y = (v00.y * (1.f - wx) + v01.y * wx) * (1.f - wy)
            + (v10.y * (1.f - wx) + v11.y * wx) * wy;
        sg[sy][sx] = r;
    }
    __syncthreads();

    int j = j0 + tx;
    int iA = i0 + ty;        // always valid (i0 <= 1072, ty <= 7)
    int iB = i0 + ty + 8;    // may exceed H-1 in last row-block

    const float stx = 0.1f * (float)(W_ - 1) / (float)W_;
    const float sty = 0.1f * (float)(H_ - 1) / (float)H_;

    float pxA = (float)j, pyA = (float)iA;
    float pxB = (float)j, pyB = (float)iB;

#pragma unroll
    for (int it = 0; it < 6; it++) {
        // chain A
        {
            float xc = fminf(fmaxf(pxA, 0.f), (float)(W_ - 1));
            float yc = fminf(fmaxf(pyA, 0.f), (float)(H_ - 1));
            int x0 = (int)xc, y0 = (int)yc;
            float wx = xc - (float)x0, wy = yc - (float)y0;
            int sx0 = x0 - (j0 - 1), sy0 = y0 - (i0 - 1);
            float2 v00 = sg[sy0][sx0],     v01 = sg[sy0][sx0 + 1];
            float2 v10 = sg[sy0 + 1][sx0], v11 = sg[sy0 + 1][sx0 + 1];
            float dx = (v00.x * (1.f - wx) + v01.x * wx) * (1.f - wy)
                     + (v10.x * (1.f - wx) + v11.x * wx) * wy;
            float dy = (v00.y * (1.f - wx) + v01.y * wx) * (1.f - wy)
                     + (v10.y * (1.f - wx) + v11.y * wx) * wy;
            float inv = 1.f / (sqrtf(dx * dx + dy * dy) + 0.01f);
            pxA -= dx * inv * stx;
            pyA -= dy * inv * sty;
        }
        // chain B (independent)
        {
            float xc = fminf(fmaxf(pxB, 0.f), (float)(W_ - 1));
            float yc = fminf(fmaxf(pyB, 0.f), (float)(H_ - 1));
            int x0 = (int)xc, y0 = (int)yc;
            float wx = xc - (float)x0, wy = yc - (float)y0;
            int sx0 = x0 - (j0 - 1), sy0 = y0 - (i0 - 1);
            // clamp smem row for invalid B rows (i >= H): sy0 <= SMH-2
            sy0 = min(sy0, SMH - 2);
            float2 v00 = sg[sy0][sx0],     v01 = sg[sy0][sx0 + 1];
            float2 v10 = sg[sy0 + 1][sx0], v11 = sg[sy0 + 1][sx0 + 1];
            float dx = (v00.x * (1.f - wx) + v01.x * wx) * (1.f - wy)
                     + (v10.x * (1.f - wx) + v11.x * wx) * wy;
            float dy = (v00.y * (1.f - wx) + v01.y * wx) * (1.f - wy)
                     + (v10.y * (1.f - wx) + v11.y * wx) * wy;
            float inv = 1.f / (sqrtf(dx * dx + dy * dy) + 0.01f);
            pxB -= dx * inv * stx;
            pyB -= dy * inv * sty;
        }
    }

    // final image sample (3 channels) + clip, both rows
#pragma unroll
    for (int s = 0; s < 2; s++) {
        int i = (s == 0) ? iA : iB;
        if (i >= H_) break;
        float px = (s == 0) ? pxA : pxB;
        float py = (s == 0) ? pyA : pyB;

        float xc = fminf(fmaxf(px, 0.f), (float)(W_ - 1));
        float yc = fminf(fmaxf(py, 0.f), (float)(H_ - 1));
        int x0 = (int)xc, y0 = (int)yc;
        int x1 = min(x0 + 1, W_ - 1), y1 = min(y0 + 1, H_ - 1);
        float wx = xc - (float)x0, wy = yc - (float)y0;
        float w00 = (1.f - wx) * (1.f - wy), w01 = wx * (1.f - wy);
        float w10 = (1.f - wx) * wy,         w11 = wx * wy;
        size_t i00 = (size_t)y0 * W_ + x0, i01 = (size_t)y0 * W_ + x1;
        size_t i10 = (size_t)y1 * W_ + x0, i11 = (size_t)y1 * W_ + x1;

#pragma unroll
        for (int c = 0; c < 3; c++) {
            const float* plane = img + ((size_t)b * 3 + c) * HW_;
            float v = __ldg(plane + i00) * w00 + __ldg(plane + i01) * w01
                    + __ldg(plane + i10) * w10 + __ldg(plane + i11) * w11;
            v = fminf(fmaxf(v, 0.f), 1.f);
            out[((size_t)b * 3 + c) * HW_ + (size_t)i * W_ + j] = v;
        }
    }
}

// ---------------------------------------------------------------------------
extern "C" void kernel_launch(void* const* d_in, const int* in_sizes, int n_in,
                              void* d_out, int out_size) {
    const float* img = (const float*)d_in[0];
    float* out = (float*)d_out;

    dim3 blk(32, 8, 1);
    dim3 gridL((SW_ + 31) / 32, (SH_ + 7) / 8, B_);
    dim3 gridS((SW_ + 31) / 32, (SH_ + 31) / 32, B_);
    dim3 gridF(W_ / 32, (H_ + 15) / 16, B_);

    k_luma_half <<<gridL, blk>>>(img);
    k_field     <<<gridS, blk>>>();
    k_warp_fused<<<gridF, blk>>>(img, out);
}